// round 2
// baseline (speedup 1.0000x reference)
#include <cuda_runtime.h>
#include <math.h>

// Problem constants
#define BSZ  2
#define NND  2048
#define FIN  128
#define H1C  8
#define F1C  64
#define HF1  512      // H1*F1
#define F2C  64
#define MROW 4096     // BSZ*NND
#define MAXN 256      // neighbor capacity per row (mean ~42)

// ---------------- scratch (static device memory; no allocs) ----------------
__device__ float g_proj1[BSZ*NND*HF1];
__device__ float g_skip1[BSZ*NND*HF1];
__device__ float g_h1  [BSZ*NND*HF1];
__device__ float g_proj2[BSZ*NND*F2C];
__device__ float g_skip2[BSZ*NND*F2C];
__device__ float g_ssrc1[MROW*H1C];
__device__ float g_stgt1[MROW*H1C];
__device__ float g_ssrc2[MROW];
__device__ float g_stgt2[MROW];
__device__ int   g_nbrs[MROW*MAXN];
__device__ int   g_cnt [MROW];

// ---------------- neighbor list build (once; reused by both layers) --------
// One block of 256 threads per (row i, batch b). Deterministic compaction via
// ballot + warp prefix scan -> g_nbrs / g_cnt.
__global__ void build_nbrs(const float* __restrict__ adj) {
    __shared__ unsigned int words[64];

    const int i    = blockIdx.x;
    const int b    = blockIdx.y;
    const int tid  = threadIdx.x;
    const int lane = tid & 31;
    const int wid  = tid >> 5;
    const int row  = b * NND + i;

    const size_t arow = ((size_t)b * NND + i) * NND;
    #pragma unroll
    for (int it = 0; it < 8; ++it) {
        int j = (((wid << 3) + it) << 5) + lane;
        float av = adj[arow + j];
        unsigned m = __ballot_sync(0xffffffffu, av != 0.0f);
        if (lane == 0) words[(wid << 3) + it] = m;
    }
    __syncthreads();

    if (wid == 0) {
        int base = 0;
        #pragma unroll
        for (int r = 0; r < 2; ++r) {
            unsigned w = words[(r << 5) + lane];
            int c = __popc(w);
            int inc = c;
            #pragma unroll
            for (int d = 1; d < 32; d <<= 1) {
                int v = __shfl_up_sync(0xffffffffu, inc, d);
                if (lane >= d) inc += v;
            }
            int start = base + inc - c;            // exclusive offset
            int jb = (((r << 5) + lane) << 5);
            unsigned ww = w;
            while (ww) {
                int bit = __ffs(ww) - 1;
                ww &= ww - 1;
                if (start < MAXN) g_nbrs[(size_t)row * MAXN + start] = jb + bit;
                ++start;
            }
            base += __shfl_sync(0xffffffffu, inc, 31);
        }
        if (lane == 0) g_cnt[row] = (base < MAXN) ? base : MAXN;
    }
}

// ---------------- dual-output GEMM: C = A @ [B0;B1]^T ----------------------
// A [M,K] row-major; B0,B1 [N0,K]/[N1,K] row-major; 64x64 tile, 256 thr, 4x4.
template<int LAYER>
__global__ void gemm_dual(const float* __restrict__ Aarg,
                          const float* __restrict__ B0,
                          const float* __restrict__ B1) {
    constexpr int K  = (LAYER == 1) ? FIN : HF1;
    constexpr int N0 = (LAYER == 1) ? HF1 : F2C;
    constexpr int N1 = N0;
    const float* __restrict__ A  = (LAYER == 1) ? Aarg : g_h1;
    float* __restrict__ C0 = (LAYER == 1) ? g_proj1 : g_proj2;
    float* __restrict__ C1 = (LAYER == 1) ? g_skip1 : g_skip2;

    __shared__ __align__(16) float As[64][33];   // [m][k]
    __shared__ __align__(16) float Bs[32][68];   // [k][o]

    const int tid = threadIdx.x;
    const int tx = tid & 15;
    const int ty = tid >> 4;
    const int m0 = blockIdx.y << 6;
    const int n0 = blockIdx.x << 6;

    float acc[4][4] = {};

    for (int kt = 0; kt < K; kt += 32) {
        #pragma unroll
        for (int l = 0; l < 8; ++l) {
            int idx = tid + l * 256;          // 0..2047
            int r   = idx >> 5;               // 0..63
            int k   = idx & 31;               // 0..31
            As[r][k] = A[(size_t)(m0 + r) * K + kt + k];
            int og = n0 + r;
            const float* Bp = (og < N0) ? (B0 + (size_t)og * K)
                                        : (B1 + (size_t)(og - N0) * K);
            Bs[k][r] = Bp[kt + k];
        }
        __syncthreads();

        #pragma unroll
        for (int k = 0; k < 32; ++k) {
            float4 b4 = *reinterpret_cast<const float4*>(&Bs[k][tx << 2]);
            float bv[4] = { b4.x, b4.y, b4.z, b4.w };
            float av[4];
            #pragma unroll
            for (int r = 0; r < 4; ++r) av[r] = As[(ty << 2) + r][k];
            #pragma unroll
            for (int r = 0; r < 4; ++r)
                #pragma unroll
                for (int c = 0; c < 4; ++c)
                    acc[r][c] += av[r] * bv[c];
        }
        __syncthreads();
    }

    #pragma unroll
    for (int r = 0; r < 4; ++r) {
        int m = m0 + (ty << 2) + r;
        #pragma unroll
        for (int c = 0; c < 4; ++c) {
            int og = n0 + (tx << 2) + c;
            float v = acc[r][c];
            if (og < N0) C0[(size_t)m * N0 + og] = v;
            else         C1[(size_t)m * N1 + og - N0] = v;
        }
    }
}

// ---------------- attention scores: s_src/s_tgt = proj . a ------------------
template<int LAYER>
__global__ void scores_kernel(const float* __restrict__ a_src,
                              const float* __restrict__ a_tgt) {
    constexpr int H = (LAYER == 1) ? H1C : 1;
    constexpr int F = 64;
    const float* __restrict__ proj = (LAYER == 1) ? g_proj1 : g_proj2;
    float* __restrict__ s_src = (LAYER == 1) ? g_ssrc1 : g_ssrc2;
    float* __restrict__ s_tgt = (LAYER == 1) ? g_stgt1 : g_stgt2;

    int idx = blockIdx.x * blockDim.x + threadIdx.x;
    if (idx >= MROW * H) return;
    int row = idx / H, h = idx % H;
    const float* p  = proj + (size_t)row * H * F + (size_t)h * F;
    const float* as = a_src + (size_t)h * F;
    const float* at = a_tgt + (size_t)h * F;
    float ss = 0.f, st = 0.f;
    #pragma unroll 8
    for (int f = 0; f < F; ++f) {
        float v = p[f];
        ss += v * as[f];
        st += v * at[f];
    }
    s_src[idx] = ss;
    s_tgt[idx] = st;
}

// ---------------- sparse GAT attention (one block per (row, batch)) --------
// blockDim = 32*H. Warp h: softmax for head h over nbr list, then all threads
// do the float2 weighted gather (head = warp id), + skip + bias + activation.
template<int LAYER>
__global__ void att_kernel(const float* __restrict__ bias,
                           float* __restrict__ out_arg) {
    constexpr int  H   = (LAYER == 1) ? H1C : 1;
    constexpr int  F   = 64;
    constexpr int  HF  = H * F;
    constexpr bool ELU = (LAYER == 1);
    const float* __restrict__ proj = (LAYER == 1) ? g_proj1 : g_proj2;
    const float* __restrict__ skip = (LAYER == 1) ? g_skip1 : g_skip2;
    const float* __restrict__ ssrc = (LAYER == 1) ? g_ssrc1 : g_ssrc2;
    const float* __restrict__ stgt = (LAYER == 1) ? g_stgt1 : g_stgt2;
    float* __restrict__ out = (LAYER == 1) ? g_h1 : out_arg;

    __shared__ int   nbrs[MAXN];
    __shared__ float wts[H * MAXN];

    const int i    = blockIdx.x;
    const int b    = blockIdx.y;
    const int tid  = threadIdx.x;
    const int lane = tid & 31;
    const int wid  = tid >> 5;
    const int row  = b * NND + i;

    const int cnt = g_cnt[row];
    for (int n = tid; n < cnt; n += 32 * H)
        nbrs[n] = g_nbrs[(size_t)row * MAXN + n];
    __syncthreads();

    // --- per-head softmax over neighbors (warp h = head h) ---
    {
        const int h = wid;
        const float si = ssrc[(size_t)row * H + h];
        float mx = -3.0e38f;
        for (int n = lane; n < cnt; n += 32) {
            int j = nbrs[n];
            float e = si + stgt[((size_t)b * NND + j) * H + h];
            e = (e > 0.f) ? e : 0.2f * e;          // leaky_relu(0.2)
            wts[h * MAXN + n] = e;
            mx = fmaxf(mx, e);
        }
        #pragma unroll
        for (int d = 16; d; d >>= 1) mx = fmaxf(mx, __shfl_xor_sync(0xffffffffu, mx, d));
        float sum = 0.f;
        for (int n = lane; n < cnt; n += 32) {
            float e = expf(wts[h * MAXN + n] - mx);
            wts[h * MAXN + n] = e;
            sum += e;
        }
        #pragma unroll
        for (int d = 16; d; d >>= 1) sum += __shfl_xor_sync(0xffffffffu, sum, d);
        float inv = 1.0f / sum;
        for (int n = lane; n < cnt; n += 32) wts[h * MAXN + n] *= inv;
    }
    __syncthreads();

    // --- float2 weighted gather; thread owns features [2*tid, 2*tid+1] ---
    {
        const int p2 = tid << 1;                  // feature pair base; head = wid
        const float* wp = &wts[wid * MAXN];
        float2 acc = make_float2(0.f, 0.f);
        const size_t brow = (size_t)b * NND;
        for (int n = 0; n < cnt; ++n) {
            float w = wp[n];
            const float2 v = *reinterpret_cast<const float2*>(
                proj + (brow + nbrs[n]) * HF + p2);
            acc.x += w * v.x;
            acc.y += w * v.y;
        }
        const float2 sk = *reinterpret_cast<const float2*>(
            skip + (size_t)row * HF + p2);
        const float2 bb = *reinterpret_cast<const float2*>(bias + p2);
        float vx = acc.x + sk.x + bb.x;
        float vy = acc.y + sk.y + bb.y;
        if (ELU) {
            vx = (vx > 0.f) ? vx : expm1f(vx);
            vy = (vy > 0.f) ? vy : expm1f(vy);
        }
        *reinterpret_cast<float2*>(out + (size_t)row * HF + p2)
            = make_float2(vx, vy);
    }
}

// ---------------------------------------------------------------------------
extern "C" void kernel_launch(void* const* d_in, const int* in_sizes, int n_in,
                              void* d_out, int out_size) {
    const float* x     = (const float*)d_in[0];
    const float* adj   = (const float*)d_in[1];
    const float* W1    = (const float*)d_in[2];
    const float* asrc1 = (const float*)d_in[3];
    const float* atgt1 = (const float*)d_in[4];
    const float* Wsk1  = (const float*)d_in[5];
    const float* b1    = (const float*)d_in[6];
    const float* W2    = (const float*)d_in[7];
    const float* asrc2 = (const float*)d_in[8];
    const float* atgt2 = (const float*)d_in[9];
    const float* Wsk2  = (const float*)d_in[10];
    const float* b2    = (const float*)d_in[11];
    float* out = (float*)d_out;

    // Neighbor lists (shared by both layers)
    build_nbrs<<<dim3(NND, BSZ), 256>>>(adj);
    // Layer 1: proj + skip GEMM  (4096 x 1024 x 128)
    gemm_dual<1><<<dim3(16, 64), 256>>>(x, W1, Wsk1);
    // Layer 1 scores
    scores_kernel<1><<<(MROW * H1C + 255) / 256, 256>>>(asrc1, atgt1);
    // Layer 1 sparse attention + skip + bias + ELU -> g_h1
    att_kernel<1><<<dim3(NND, BSZ), 32 * H1C>>>(b1, nullptr);
    // Layer 2: proj + skip GEMM  (4096 x 128 x 512)
    gemm_dual<2><<<dim3(2, 64), 256>>>(nullptr, W2, Wsk2);
    // Layer 2 scores
    scores_kernel<2><<<(MROW + 255) / 256, 256>>>(asrc2, atgt2);
    // Layer 2 sparse attention + skip + bias (mean over 1 head = identity)
    att_kernel<2><<<dim3(NND, BSZ), 32>>>(b2, out);
}

// round 3
// speedup vs baseline: 1.3588x; 1.3588x over previous
#include <cuda_runtime.h>
#include <math.h>

// Problem constants
#define BSZ  2
#define NND  2048
#define FIN  128
#define H1C  8
#define F1C  64
#define HF1  512      // H1*F1
#define F2C  64
#define MROW 4096     // BSZ*NND
#define MAXN 128      // neighbor cap (binomial mean ~41, sd ~6.3; 128 = +13.7 sd)
#define KSPLIT 4      // split-K factor for layer-2 GEMM

// ---------------- scratch (static device memory; no allocs) ----------------
__device__ float g_proj1[BSZ*NND*HF1];
__device__ float g_skip1[BSZ*NND*HF1];
__device__ float g_h1  [BSZ*NND*HF1];
__device__ float g_proj2[BSZ*NND*F2C];
__device__ float g_skip2[BSZ*NND*F2C];
__device__ float g_ssrc1[MROW*H1C];
__device__ float g_stgt1[MROW*H1C];
__device__ float g_ssrc2[MROW];
__device__ float g_stgt2[MROW];
__device__ int   g_nbrs[MROW*MAXN];
__device__ int   g_cnt [MROW];
__device__ float g_part[KSPLIT*(size_t)MROW*128];   // split-K partials (8 MB)

// ---------------- neighbor list build (once; reused by both layers) --------
__global__ void build_nbrs(const float* __restrict__ adj) {
    __shared__ unsigned int words[64];

    const int i    = blockIdx.x;
    const int b    = blockIdx.y;
    const int tid  = threadIdx.x;
    const int lane = tid & 31;
    const int wid  = tid >> 5;
    const int row  = b * NND + i;

    const size_t arow = ((size_t)b * NND + i) * NND;
    #pragma unroll
    for (int it = 0; it < 8; ++it) {
        int j = (((wid << 3) + it) << 5) + lane;
        float av = adj[arow + j];
        unsigned m = __ballot_sync(0xffffffffu, av != 0.0f);
        if (lane == 0) words[(wid << 3) + it] = m;
    }
    __syncthreads();

    if (wid == 0) {
        int base = 0;
        #pragma unroll
        for (int r = 0; r < 2; ++r) {
            unsigned w = words[(r << 5) + lane];
            int c = __popc(w);
            int inc = c;
            #pragma unroll
            for (int d = 1; d < 32; d <<= 1) {
                int v = __shfl_up_sync(0xffffffffu, inc, d);
                if (lane >= d) inc += v;
            }
            int start = base + inc - c;            // exclusive offset
            int jb = (((r << 5) + lane) << 5);
            unsigned ww = w;
            while (ww) {
                int bit = __ffs(ww) - 1;
                ww &= ww - 1;
                if (start < MAXN) g_nbrs[(size_t)row * MAXN + start] = jb + bit;
                ++start;
            }
            base += __shfl_sync(0xffffffffu, inc, 31);
        }
        if (lane == 0) g_cnt[row] = (base < MAXN) ? base : MAXN;
    }
}

// ---------------- 128x128 GEMM: C = A @ [B0;B1]^T, optional split-K --------
// A [M,K] row-major; B0 [N0,K], B1 row-major. 256 threads, 8x8 microtile.
// Thread owns rows {4ty..4ty+3, 64+4ty..}, cols {4tx.., 64+4tx..} (conflict-
// free LDS.128 on both operands). If SPLIT, write partials to g_part[z].
template<int K, int KC, int N0, bool SPLIT>
__global__ void gemm128(const float* __restrict__ A,
                        const float* __restrict__ B0,
                        const float* __restrict__ B1,
                        float* __restrict__ C0,
                        float* __restrict__ C1) {
    __shared__ __align__(16) float As[16][132];   // [k][m]
    __shared__ __align__(16) float Bs[16][132];   // [k][n]

    const int tid = threadIdx.x;
    const int tx  = tid & 15;
    const int ty  = tid >> 4;
    const int m0  = blockIdx.y << 7;
    const int n0  = blockIdx.x << 7;
    const int kz  = blockIdx.z * KC;

    float acc[8][8];
    #pragma unroll
    for (int r = 0; r < 8; ++r)
        #pragma unroll
        for (int c = 0; c < 8; ++c) acc[r][c] = 0.f;

    for (int kt = kz; kt < kz + KC; kt += 16) {
        // Load 128x16 A and B tiles as [k][m]/[k][n] (512 float4 each).
        #pragma unroll
        for (int l = 0; l < 2; ++l) {
            int idx = tid + (l << 8);             // 0..511
            int r   = idx >> 2;                   // 0..127
            int kq  = (idx & 3) << 2;             // 0,4,8,12
            float4 av = *reinterpret_cast<const float4*>(
                A + (size_t)(m0 + r) * K + kt + kq);
            As[kq+0][r] = av.x; As[kq+1][r] = av.y;
            As[kq+2][r] = av.z; As[kq+3][r] = av.w;
            int og = n0 + r;
            const float* Bp = (og < N0) ? (B0 + (size_t)og * K)
                                        : (B1 + (size_t)(og - N0) * K);
            float4 bv = *reinterpret_cast<const float4*>(Bp + kt + kq);
            Bs[kq+0][r] = bv.x; Bs[kq+1][r] = bv.y;
            Bs[kq+2][r] = bv.z; Bs[kq+3][r] = bv.w;
        }
        __syncthreads();

        #pragma unroll
        for (int k = 0; k < 16; ++k) {
            float4 a0 = *reinterpret_cast<const float4*>(&As[k][ty << 2]);
            float4 a1 = *reinterpret_cast<const float4*>(&As[k][64 + (ty << 2)]);
            float4 b0 = *reinterpret_cast<const float4*>(&Bs[k][tx << 2]);
            float4 b1 = *reinterpret_cast<const float4*>(&Bs[k][64 + (tx << 2)]);
            float a[8] = { a0.x, a0.y, a0.z, a0.w, a1.x, a1.y, a1.z, a1.w };
            float bb[8] = { b0.x, b0.y, b0.z, b0.w, b1.x, b1.y, b1.z, b1.w };
            #pragma unroll
            for (int r = 0; r < 8; ++r)
                #pragma unroll
                for (int c = 0; c < 8; ++c)
                    acc[r][c] += a[r] * bb[c];
        }
        __syncthreads();
    }

    #pragma unroll
    for (int r = 0; r < 8; ++r) {
        int m = m0 + ((r & 4) << 4) + (ty << 2) + (r & 3);   // +64 if r>=4
        #pragma unroll
        for (int ch = 0; ch < 2; ++ch) {
            int colloc = (ch << 6) + (tx << 2);               // 0..127
            float4 v = make_float4(acc[r][(ch<<2)+0], acc[r][(ch<<2)+1],
                                   acc[r][(ch<<2)+2], acc[r][(ch<<2)+3]);
            if (SPLIT) {
                *reinterpret_cast<float4*>(
                    g_part + ((size_t)blockIdx.z * MROW + m) * 128 + colloc) = v;
            } else {
                int og = n0 + colloc;
                if (og < N0)
                    *reinterpret_cast<float4*>(C0 + (size_t)m * N0 + og) = v;
                else
                    *reinterpret_cast<float4*>(C1 + (size_t)m * N0 + og - N0) = v;
            }
        }
    }
}

// ---------------- split-K reduce -> proj2 / skip2 --------------------------
__global__ void reduce_split() {
    int idx = blockIdx.x * blockDim.x + threadIdx.x;    // over MROW*128
    int m = idx >> 7, c = idx & 127;
    float s = 0.f;
    #pragma unroll
    for (int z = 0; z < KSPLIT; ++z)
        s += g_part[((size_t)z * MROW + m) * 128 + c];
    if (c < 64) g_proj2[(size_t)m * 64 + c] = s;
    else        g_skip2[(size_t)m * 64 + c - 64] = s;
}

// ---------------- attention scores: warp per (row, head) -------------------
template<int LAYER>
__global__ void scores_kernel(const float* __restrict__ a_src,
                              const float* __restrict__ a_tgt) {
    const float* __restrict__ proj = (LAYER == 1) ? g_proj1 : g_proj2;
    float* __restrict__ s_src = (LAYER == 1) ? g_ssrc1 : g_ssrc2;
    float* __restrict__ s_tgt = (LAYER == 1) ? g_stgt1 : g_stgt2;

    const int lane = threadIdx.x & 31;
    const int wid  = threadIdx.x >> 5;
    int row, h;
    if (LAYER == 1) { row = blockIdx.x;            h = wid; }
    else            { row = blockIdx.x * 8 + wid;  h = 0;   }

    const float* p = proj + ((size_t)row * ((LAYER == 1) ? H1C : 1) + h) * 64;
    float v0 = p[lane], v1 = p[lane + 32];
    const float* as = a_src + h * 64;
    const float* at = a_tgt + h * 64;
    float ss = v0 * as[lane] + v1 * as[lane + 32];
    float st = v0 * at[lane] + v1 * at[lane + 32];
    #pragma unroll
    for (int d = 16; d; d >>= 1) {
        ss += __shfl_xor_sync(0xffffffffu, ss, d);
        st += __shfl_xor_sync(0xffffffffu, st, d);
    }
    if (lane == 0) {
        int idx = (LAYER == 1) ? row * H1C + h : row;
        s_src[idx] = ss;
        s_tgt[idx] = st;
    }
}

// ---------------- layer-1 attention: 128 thr/block, float4 gather ----------
__global__ void att1_kernel(const float* __restrict__ bias) {
    __shared__ int   nbrs[MAXN];
    __shared__ float wts[H1C][MAXN];

    const int i    = blockIdx.x;
    const int b    = blockIdx.y;
    const int tid  = threadIdx.x;
    const int lane = tid & 31;
    const int wid  = tid >> 5;           // 0..3
    const int row  = b * NND + i;

    const int cnt = g_cnt[row];
    for (int n = tid; n < cnt; n += 128)
        nbrs[n] = g_nbrs[(size_t)row * MAXN + n];
    __syncthreads();

    // softmax: warp w handles heads 2w, 2w+1
    #pragma unroll
    for (int hh = 0; hh < 2; ++hh) {
        const int h = (wid << 1) + hh;
        const float si = g_ssrc1[(size_t)row * H1C + h];
        float mx = -3.0e38f;
        for (int n = lane; n < cnt; n += 32) {
            int j = nbrs[n];
            float e = si + g_stgt1[((size_t)b * NND + j) * H1C + h];
            e = (e > 0.f) ? e : 0.2f * e;          // leaky_relu(0.2)
            wts[h][n] = e;
            mx = fmaxf(mx, e);
        }
        #pragma unroll
        for (int d = 16; d; d >>= 1)
            mx = fmaxf(mx, __shfl_xor_sync(0xffffffffu, mx, d));
        float sum = 0.f;
        for (int n = lane; n < cnt; n += 32) {
            float e = expf(wts[h][n] - mx);
            wts[h][n] = e;
            sum += e;
        }
        #pragma unroll
        for (int d = 16; d; d >>= 1)
            sum += __shfl_xor_sync(0xffffffffu, sum, d);
        float inv = 1.0f / sum;
        for (int n = lane; n < cnt; n += 32) wts[h][n] *= inv;
    }
    __syncthreads();

    // gather: thread owns 4 contiguous features; head = tid>>4
    const int h = tid >> 4;
    const int p = (h << 6) + ((tid & 15) << 2);
    const float* wp = wts[h];
    const size_t brow = (size_t)b * NND;
    float4 acc0 = make_float4(0.f, 0.f, 0.f, 0.f);
    float4 acc1 = make_float4(0.f, 0.f, 0.f, 0.f);
    int n = 0;
    for (; n + 1 < cnt; n += 2) {
        float w0 = wp[n], w1 = wp[n + 1];
        float4 v0 = *reinterpret_cast<const float4*>(
            g_proj1 + (brow + nbrs[n]) * HF1 + p);
        float4 v1 = *reinterpret_cast<const float4*>(
            g_proj1 + (brow + nbrs[n + 1]) * HF1 + p);
        acc0.x += w0 * v0.x; acc0.y += w0 * v0.y;
        acc0.z += w0 * v0.z; acc0.w += w0 * v0.w;
        acc1.x += w1 * v1.x; acc1.y += w1 * v1.y;
        acc1.z += w1 * v1.z; acc1.w += w1 * v1.w;
    }
    if (n < cnt) {
        float w0 = wp[n];
        float4 v0 = *reinterpret_cast<const float4*>(
            g_proj1 + (brow + nbrs[n]) * HF1 + p);
        acc0.x += w0 * v0.x; acc0.y += w0 * v0.y;
        acc0.z += w0 * v0.z; acc0.w += w0 * v0.w;
    }
    float4 sk = *reinterpret_cast<const float4*>(g_skip1 + (size_t)row * HF1 + p);
    float4 bb = *reinterpret_cast<const float4*>(bias + p);
    float4 o;
    o.x = acc0.x + acc1.x + sk.x + bb.x;
    o.y = acc0.y + acc1.y + sk.y + bb.y;
    o.z = acc0.z + acc1.z + sk.z + bb.z;
    o.w = acc0.w + acc1.w + sk.w + bb.w;
    o.x = (o.x > 0.f) ? o.x : expm1f(o.x);
    o.y = (o.y > 0.f) ? o.y : expm1f(o.y);
    o.z = (o.z > 0.f) ? o.z : expm1f(o.z);
    o.w = (o.w > 0.f) ? o.w : expm1f(o.w);
    *reinterpret_cast<float4*>(g_h1 + (size_t)row * HF1 + p) = o;
}

// ---------------- layer-2 attention: warp per row, 4 rows/block ------------
__global__ void att2_kernel(const float* __restrict__ bias,
                            float* __restrict__ out) {
    __shared__ int   nbrs[4][MAXN];
    __shared__ float wts[4][MAXN];

    const int b    = blockIdx.y;
    const int tid  = threadIdx.x;
    const int lane = tid & 31;
    const int wid  = tid >> 5;           // 0..3
    const int i    = (blockIdx.x << 2) + wid;
    const int row  = b * NND + i;

    const int cnt = g_cnt[row];
    for (int n = lane; n < cnt; n += 32)
        nbrs[wid][n] = g_nbrs[(size_t)row * MAXN + n];
    __syncwarp();

    // softmax (single head)
    {
        const float si = g_ssrc2[row];
        float mx = -3.0e38f;
        for (int n = lane; n < cnt; n += 32) {
            int j = nbrs[wid][n];
            float e = si + g_stgt2[(size_t)b * NND + j];
            e = (e > 0.f) ? e : 0.2f * e;
            wts[wid][n] = e;
            mx = fmaxf(mx, e);
        }
        #pragma unroll
        for (int d = 16; d; d >>= 1)
            mx = fmaxf(mx, __shfl_xor_sync(0xffffffffu, mx, d));
        float sum = 0.f;
        for (int n = lane; n < cnt; n += 32) {
            float e = expf(wts[wid][n] - mx);
            wts[wid][n] = e;
            sum += e;
        }
        #pragma unroll
        for (int d = 16; d; d >>= 1)
            sum += __shfl_xor_sync(0xffffffffu, sum, d);
        float inv = 1.0f / sum;
        for (int n = lane; n < cnt; n += 32) wts[wid][n] *= inv;
    }
    __syncwarp();

    // gather: thread owns 2 contiguous features
    const int p = lane << 1;
    const size_t brow = (size_t)b * NND;
    float2 acc0 = make_float2(0.f, 0.f);
    float2 acc1 = make_float2(0.f, 0.f);
    int n = 0;
    for (; n + 1 < cnt; n += 2) {
        float w0 = wts[wid][n], w1 = wts[wid][n + 1];
        float2 v0 = *reinterpret_cast<const float2*>(
            g_proj2 + (brow + nbrs[wid][n]) * F2C + p);
        float2 v1 = *reinterpret_cast<const float2*>(
            g_proj2 + (brow + nbrs[wid][n + 1]) * F2C + p);
        acc0.x += w0 * v0.x; acc0.y += w0 * v0.y;
        acc1.x += w1 * v1.x; acc1.y += w1 * v1.y;
    }
    if (n < cnt) {
        float w0 = wts[wid][n];
        float2 v0 = *reinterpret_cast<const float2*>(
            g_proj2 + (brow + nbrs[wid][n]) * F2C + p);
        acc0.x += w0 * v0.x; acc0.y += w0 * v0.y;
    }
    float2 sk = *reinterpret_cast<const float2*>(g_skip2 + (size_t)row * F2C + p);
    float2 bb = *reinterpret_cast<const float2*>(bias + p);
    float2 o = make_float2(acc0.x + acc1.x + sk.x + bb.x,
                           acc0.y + acc1.y + sk.y + bb.y);
    *reinterpret_cast<float2*>(out + (size_t)row * F2C + p) = o;
}

// ---------------------------------------------------------------------------
extern "C" void kernel_launch(void* const* d_in, const int* in_sizes, int n_in,
                              void* d_out, int out_size) {
    const float* x     = (const float*)d_in[0];
    const float* adj   = (const float*)d_in[1];
    const float* W1    = (const float*)d_in[2];
    const float* asrc1 = (const float*)d_in[3];
    const float* atgt1 = (const float*)d_in[4];
    const float* Wsk1  = (const float*)d_in[5];
    const float* b1    = (const float*)d_in[6];
    const float* W2    = (const float*)d_in[7];
    const float* asrc2 = (const float*)d_in[8];
    const float* atgt2 = (const float*)d_in[9];
    const float* Wsk2  = (const float*)d_in[10];
    const float* b2    = (const float*)d_in[11];
    float* out = (float*)d_out;

    float *proj1, *skip1, *h1;
    cudaGetSymbolAddress((void**)&proj1, g_proj1);
    cudaGetSymbolAddress((void**)&skip1, g_skip1);
    cudaGetSymbolAddress((void**)&h1,    g_h1);

    // Neighbor lists (shared by both layers)
    build_nbrs<<<dim3(NND, BSZ), 256>>>(adj);
    // Layer 1: proj+skip GEMM (4096 x 1024 x 128), direct write
    gemm128<FIN, FIN, HF1, false><<<dim3(8, 32, 1), 256>>>(x, W1, Wsk1,
                                                           proj1, skip1);
    // Layer 1 scores (warp per (row,head))
    scores_kernel<1><<<MROW, 256>>>(asrc1, atgt1);
    // Layer 1 sparse attention + skip + bias + ELU -> g_h1
    att1_kernel<<<dim3(NND, BSZ), 128>>>(b1);
    // Layer 2: proj+skip GEMM (4096 x 128 x 512), split-K=4
    gemm128<HF1, HF1 / KSPLIT, F2C, true><<<dim3(1, 32, KSPLIT), 256>>>(
        h1, W2, Wsk2, nullptr, nullptr);
    reduce_split<<<(MROW * 128) / 256, 256>>>();
    // Layer 2 scores
    scores_kernel<2><<<MROW / 8, 256>>>(asrc2, atgt2);
    // Layer 2 sparse attention + skip + bias (mean over 1 head = identity)
    att2_kernel<<<dim3(NND / 4, BSZ), 128>>>(b2, out);
}

// round 5
// speedup vs baseline: 1.3725x; 1.0101x over previous
#include <cuda_runtime.h>
#include <cuda_fp16.h>
#include <math.h>

// Problem constants
#define BSZ  2
#define NND  2048
#define FIN  128
#define H1C  8
#define F1C  64
#define HF1  512      // H1*F1
#define F2C  64
#define MROW 4096     // BSZ*NND
#define MAXN 128      // neighbor cap (binomial mean ~41, sd ~6.3)
#define KSPLIT 4      // split-K factor for layer-2 GEMM

// ---------------- scratch (static device memory; no allocs) ----------------
__device__ float  g_proj1 [BSZ*NND*HF1];
__device__ __half g_proj1h[BSZ*NND*HF1];
__device__ float  g_skip1 [BSZ*NND*HF1];
__device__ float  g_h1    [BSZ*NND*HF1];
__device__ __half g_proj2h[BSZ*NND*F2C];
__device__ float  g_skip2 [BSZ*NND*F2C];
__device__ float  g_ssrc1[MROW*H1C];
__device__ float  g_stgt1[MROW*H1C];
__device__ float  g_ssrc2[MROW];
__device__ float  g_stgt2[MROW];
__device__ int    g_nbrs[MROW*MAXN];
__device__ int    g_cnt [MROW];
__device__ float  g_part[KSPLIT*(size_t)MROW*128];   // split-K partials (8 MB)

__device__ __forceinline__ float4 h4_to_f4(uint2 r) {
    __half2 a = *reinterpret_cast<__half2*>(&r.x);
    __half2 b = *reinterpret_cast<__half2*>(&r.y);
    float2 fa = __half22float2(a), fb = __half22float2(b);
    return make_float4(fa.x, fa.y, fb.x, fb.y);
}

// ---------------- neighbor list build (once; reused by both layers) --------
__global__ void build_nbrs(const float* __restrict__ adj) {
    __shared__ unsigned int words[64];

    const int i    = blockIdx.x;
    const int b    = blockIdx.y;
    const int tid  = threadIdx.x;
    const int lane = tid & 31;
    const int wid  = tid >> 5;
    const int row  = b * NND + i;

    const size_t arow = ((size_t)b * NND + i) * NND;
    #pragma unroll
    for (int it = 0; it < 8; ++it) {
        int j = (((wid << 3) + it) << 5) + lane;
        float av = adj[arow + j];
        unsigned m = __ballot_sync(0xffffffffu, av != 0.0f);
        if (lane == 0) words[(wid << 3) + it] = m;
    }
    __syncthreads();

    if (wid == 0) {
        int base = 0;
        #pragma unroll
        for (int r = 0; r < 2; ++r) {
            unsigned w = words[(r << 5) + lane];
            int c = __popc(w);
            int inc = c;
            #pragma unroll
            for (int d = 1; d < 32; d <<= 1) {
                int v = __shfl_up_sync(0xffffffffu, inc, d);
                if (lane >= d) inc += v;
            }
            int start = base + inc - c;            // exclusive offset
            int jb = (((r << 5) + lane) << 5);
            unsigned ww = w;
            while (ww) {
                int bit = __ffs(ww) - 1;
                ww &= ww - 1;
                if (start < MAXN) g_nbrs[(size_t)row * MAXN + start] = jb + bit;
                ++start;
            }
            base += __shfl_sync(0xffffffffu, inc, 31);
        }
        if (lane == 0) g_cnt[row] = (base < MAXN) ? base : MAXN;
    }
}

// ---------------- 128x128 GEMM: C = A @ [B0;B1]^T --------------------------
// 256 threads, 8x8 microtile, conflict-free split-quad layout.
// SPLIT: write partials to g_part. WRITEH: also store fp16 copy of C0 cols.
template<int K, int KC, int N0, bool SPLIT, bool WRITEH>
__global__ void __launch_bounds__(256)
gemm128(const float* __restrict__ A,
        const float* __restrict__ B0,
        const float* __restrict__ B1,
        float* __restrict__ C0,
        float* __restrict__ C1) {
    __shared__ __align__(16) float As[16][132];   // [k][m]
    __shared__ __align__(16) float Bs[16][132];   // [k][n]

    const int tid = threadIdx.x;
    const int tx  = tid & 15;
    const int ty  = tid >> 4;
    const int m0  = blockIdx.y << 7;
    const int n0  = blockIdx.x << 7;
    const int kz  = blockIdx.z * KC;

    float acc[8][8];
    #pragma unroll
    for (int r = 0; r < 8; ++r)
        #pragma unroll
        for (int c = 0; c < 8; ++c) acc[r][c] = 0.f;

    for (int kt = kz; kt < kz + KC; kt += 16) {
        #pragma unroll
        for (int l = 0; l < 2; ++l) {
            int idx = tid + (l << 8);             // 0..511
            int r   = idx >> 2;                   // 0..127
            int kq  = (idx & 3) << 2;             // 0,4,8,12
            float4 av = *reinterpret_cast<const float4*>(
                A + (size_t)(m0 + r) * K + kt + kq);
            As[kq+0][r] = av.x; As[kq+1][r] = av.y;
            As[kq+2][r] = av.z; As[kq+3][r] = av.w;
            int og = n0 + r;
            const float* Bp = (og < N0) ? (B0 + (size_t)og * K)
                                        : (B1 + (size_t)(og - N0) * K);
            float4 bv = *reinterpret_cast<const float4*>(Bp + kt + kq);
            Bs[kq+0][r] = bv.x; Bs[kq+1][r] = bv.y;
            Bs[kq+2][r] = bv.z; Bs[kq+3][r] = bv.w;
        }
        __syncthreads();

        #pragma unroll
        for (int k = 0; k < 16; ++k) {
            float4 a0 = *reinterpret_cast<const float4*>(&As[k][ty << 2]);
            float4 a1 = *reinterpret_cast<const float4*>(&As[k][64 + (ty << 2)]);
            float4 b0 = *reinterpret_cast<const float4*>(&Bs[k][tx << 2]);
            float4 b1 = *reinterpret_cast<const float4*>(&Bs[k][64 + (tx << 2)]);
            float a[8] = { a0.x, a0.y, a0.z, a0.w, a1.x, a1.y, a1.z, a1.w };
            float bb[8] = { b0.x, b0.y, b0.z, b0.w, b1.x, b1.y, b1.z, b1.w };
            #pragma unroll
            for (int r = 0; r < 8; ++r)
                #pragma unroll
                for (int c = 0; c < 8; ++c)
                    acc[r][c] += a[r] * bb[c];
        }
        __syncthreads();
    }

    #pragma unroll
    for (int r = 0; r < 8; ++r) {
        int m = m0 + ((r & 4) << 4) + (ty << 2) + (r & 3);   // +64 if r>=4
        #pragma unroll
        for (int ch = 0; ch < 2; ++ch) {
            int colloc = (ch << 6) + (tx << 2);               // 0..127
            float4 v = make_float4(acc[r][(ch<<2)+0], acc[r][(ch<<2)+1],
                                   acc[r][(ch<<2)+2], acc[r][(ch<<2)+3]);
            if (SPLIT) {
                *reinterpret_cast<float4*>(
                    g_part + ((size_t)blockIdx.z * MROW + m) * 128 + colloc) = v;
            } else {
                int og = n0 + colloc;
                if (og < N0) {
                    *reinterpret_cast<float4*>(C0 + (size_t)m * N0 + og) = v;
                    if (WRITEH) {
                        __half2 h01 = __floats2half2_rn(v.x, v.y);
                        __half2 h23 = __floats2half2_rn(v.z, v.w);
                        uint2 pk;
                        pk.x = *reinterpret_cast<unsigned int*>(&h01);
                        pk.y = *reinterpret_cast<unsigned int*>(&h23);
                        *reinterpret_cast<uint2*>(
                            g_proj1h + (size_t)m * N0 + og) = pk;
                    }
                } else {
                    *reinterpret_cast<float4*>(C1 + (size_t)m * N0 + og - N0) = v;
                }
            }
        }
    }
}

// ---------------- layer-1 attention scores: warp per (row, head) -----------
__global__ void scores1_kernel(const float* __restrict__ a_src,
                               const float* __restrict__ a_tgt) {
    const int lane = threadIdx.x & 31;
    const int wid  = threadIdx.x >> 5;
    const int row  = blockIdx.x;
    const int h    = wid;

    const float* p = g_proj1 + ((size_t)row * H1C + h) * 64;
    float v0 = p[lane], v1 = p[lane + 32];
    const float* as = a_src + h * 64;
    const float* at = a_tgt + h * 64;
    float ss = v0 * as[lane] + v1 * as[lane + 32];
    float st = v0 * at[lane] + v1 * at[lane + 32];
    #pragma unroll
    for (int d = 16; d; d >>= 1) {
        ss += __shfl_xor_sync(0xffffffffu, ss, d);
        st += __shfl_xor_sync(0xffffffffu, st, d);
    }
    if (lane == 0) {
        g_ssrc1[row * H1C + h] = ss;
        g_stgt1[row * H1C + h] = st;
    }
}

// ---------------- layer-1 attention: fp16 gather, MLP=4 --------------------
__global__ void __launch_bounds__(128)
att1_kernel(const float* __restrict__ bias) {
    __shared__ int   nbrs[MAXN];
    __shared__ float wts[H1C][MAXN];

    const int i    = blockIdx.x;
    const int b    = blockIdx.y;
    const int tid  = threadIdx.x;
    const int lane = tid & 31;
    const int wid  = tid >> 5;           // 0..3
    const int row  = b * NND + i;

    const int cnt = g_cnt[row];
    for (int n = tid; n < cnt; n += 128)
        nbrs[n] = g_nbrs[(size_t)row * MAXN + n];
    __syncthreads();

    // softmax: warp w handles heads 2w, 2w+1 (fp32 scores)
    #pragma unroll
    for (int hh = 0; hh < 2; ++hh) {
        const int h = (wid << 1) + hh;
        const float si = g_ssrc1[(size_t)row * H1C + h];
        float mx = -3.0e38f;
        for (int n = lane; n < cnt; n += 32) {
            int j = nbrs[n];
            float e = si + g_stgt1[((size_t)b * NND + j) * H1C + h];
            e = (e > 0.f) ? e : 0.2f * e;          // leaky_relu(0.2)
            wts[h][n] = e;
            mx = fmaxf(mx, e);
        }
        #pragma unroll
        for (int d = 16; d; d >>= 1)
            mx = fmaxf(mx, __shfl_xor_sync(0xffffffffu, mx, d));
        float sum = 0.f;
        for (int n = lane; n < cnt; n += 32) {
            float e = expf(wts[h][n] - mx);
            wts[h][n] = e;
            sum += e;
        }
        #pragma unroll
        for (int d = 16; d; d >>= 1)
            sum += __shfl_xor_sync(0xffffffffu, sum, d);
        float inv = 1.0f / sum;
        for (int n = lane; n < cnt; n += 32) wts[h][n] *= inv;
    }
    __syncthreads();

    // gather: thread owns 4 contiguous features (8B fp16); head = tid>>4
    const int h = tid >> 4;
    const int p = (h << 6) + ((tid & 15) << 2);
    const float* wp = wts[h];
    const size_t brow = (size_t)b * NND;
    const uint2* __restrict__ ph = reinterpret_cast<const uint2*>(g_proj1h);
    const int pq = p >> 2;                         // uint2 index within row
    float4 A0 = make_float4(0,0,0,0), A1 = make_float4(0,0,0,0);
    float4 A2 = make_float4(0,0,0,0), A3 = make_float4(0,0,0,0);
    int n = 0;
    for (; n + 3 < cnt; n += 4) {
        uint2 r0 = ph[(brow + nbrs[n    ]) * (HF1/4) + pq];
        uint2 r1 = ph[(brow + nbrs[n + 1]) * (HF1/4) + pq];
        uint2 r2 = ph[(brow + nbrs[n + 2]) * (HF1/4) + pq];
        uint2 r3 = ph[(brow + nbrs[n + 3]) * (HF1/4) + pq];
        float w0 = wp[n], w1 = wp[n+1], w2 = wp[n+2], w3 = wp[n+3];
        float4 v0 = h4_to_f4(r0), v1 = h4_to_f4(r1);
        float4 v2 = h4_to_f4(r2), v3 = h4_to_f4(r3);
        A0.x += w0*v0.x; A0.y += w0*v0.y; A0.z += w0*v0.z; A0.w += w0*v0.w;
        A1.x += w1*v1.x; A1.y += w1*v1.y; A1.z += w1*v1.z; A1.w += w1*v1.w;
        A2.x += w2*v2.x; A2.y += w2*v2.y; A2.z += w2*v2.z; A2.w += w2*v2.w;
        A3.x += w3*v3.x; A3.y += w3*v3.y; A3.z += w3*v3.z; A3.w += w3*v3.w;
    }
    for (; n < cnt; ++n) {
        uint2 r0 = ph[(brow + nbrs[n]) * (HF1/4) + pq];
        float w0 = wp[n];
        float4 v0 = h4_to_f4(r0);
        A0.x += w0*v0.x; A0.y += w0*v0.y; A0.z += w0*v0.z; A0.w += w0*v0.w;
    }
    float4 sk = *reinterpret_cast<const float4*>(g_skip1 + (size_t)row * HF1 + p);
    float4 bb = *reinterpret_cast<const float4*>(bias + p);
    float4 o;
    o.x = (A0.x + A1.x) + (A2.x + A3.x) + sk.x + bb.x;
    o.y = (A0.y + A1.y) + (A2.y + A3.y) + sk.y + bb.y;
    o.z = (A0.z + A1.z) + (A2.z + A3.z) + sk.z + bb.z;
    o.w = (A0.w + A1.w) + (A2.w + A3.w) + sk.w + bb.w;
    o.x = (o.x > 0.f) ? o.x : expm1f(o.x);
    o.y = (o.y > 0.f) ? o.y : expm1f(o.y);
    o.z = (o.z > 0.f) ? o.z : expm1f(o.z);
    o.w = (o.w > 0.f) ? o.w : expm1f(o.w);
    *reinterpret_cast<float4*>(g_h1 + (size_t)row * HF1 + p) = o;
}

// ------- fused split-K reduce + layer-2 scores (warp per row) --------------
// Lane L sums cols 4L..4L+3 over KSPLIT partials; cols<64 -> proj2 (fp16),
// cols>=64 -> skip2 (fp32). Then warp-dot with a_src2/a_tgt2 for scores.
__global__ void reduce_scores2(const float* __restrict__ a_src,
                               const float* __restrict__ a_tgt) {
    const int lane = threadIdx.x & 31;
    const int wid  = threadIdx.x >> 5;           // 0..7
    const int m    = (blockIdx.x << 3) + wid;

    float4 s = make_float4(0,0,0,0);
    #pragma unroll
    for (int z = 0; z < KSPLIT; ++z) {
        float4 v = *reinterpret_cast<const float4*>(
            g_part + ((size_t)z * MROW + m) * 128 + (lane << 2));
        s.x += v.x; s.y += v.y; s.z += v.z; s.w += v.w;
    }

    float ss = 0.f, st = 0.f;
    if (lane < 16) {
        // proj2 columns 4L..4L+3
        __half2 h01 = __floats2half2_rn(s.x, s.y);
        __half2 h23 = __floats2half2_rn(s.z, s.w);
        uint2 pk;
        pk.x = *reinterpret_cast<unsigned int*>(&h01);
        pk.y = *reinterpret_cast<unsigned int*>(&h23);
        *reinterpret_cast<uint2*>(g_proj2h + (size_t)m * F2C + (lane << 2)) = pk;
        float4 as = *reinterpret_cast<const float4*>(a_src + (lane << 2));
        float4 at = *reinterpret_cast<const float4*>(a_tgt + (lane << 2));
        ss = s.x*as.x + s.y*as.y + s.z*as.z + s.w*as.w;
        st = s.x*at.x + s.y*at.y + s.z*at.z + s.w*at.w;
    } else {
        // skip2 columns 4(L-16)..
        *reinterpret_cast<float4*>(
            g_skip2 + (size_t)m * F2C + ((lane - 16) << 2)) = s;
    }
    #pragma unroll
    for (int d = 16; d; d >>= 1) {
        ss += __shfl_xor_sync(0xffffffffu, ss, d);
        st += __shfl_xor_sync(0xffffffffu, st, d);
    }
    if (lane == 0) {
        g_ssrc2[m] = ss;
        g_stgt2[m] = st;
    }
}

// ---------------- layer-2 attention: warp per row, fp16 gather -------------
__global__ void __launch_bounds__(128)
att2_kernel(const float* __restrict__ bias, float* __restrict__ out) {
    __shared__ int   nbrs[4][MAXN];
    __shared__ float wts[4][MAXN];

    const int b    = blockIdx.y;
    const int tid  = threadIdx.x;
    const int lane = tid & 31;
    const int wid  = tid >> 5;           // 0..3
    const int i    = (blockIdx.x << 2) + wid;
    const int row  = b * NND + i;

    const int cnt = g_cnt[row];
    for (int n = lane; n < cnt; n += 32)
        nbrs[wid][n] = g_nbrs[(size_t)row * MAXN + n];
    __syncwarp();

    {
        const float si = g_ssrc2[row];
        float mx = -3.0e38f;
        for (int n = lane; n < cnt; n += 32) {
            int j = nbrs[wid][n];
            float e = si + g_stgt2[(size_t)b * NND + j];
            e = (e > 0.f) ? e : 0.2f * e;
            wts[wid][n] = e;
            mx = fmaxf(mx, e);
        }
        #pragma unroll
        for (int d = 16; d; d >>= 1)
            mx = fmaxf(mx, __shfl_xor_sync(0xffffffffu, mx, d));
        float sum = 0.f;
        for (int n = lane; n < cnt; n += 32) {
            float e = expf(wts[wid][n] - mx);
            wts[wid][n] = e;
            sum += e;
        }
        #pragma unroll
        for (int d = 16; d; d >>= 1)
            sum += __shfl_xor_sync(0xffffffffu, sum, d);
        float inv = 1.0f / sum;
        for (int n = lane; n < cnt; n += 32) wts[wid][n] *= inv;
    }
    __syncwarp();

    // gather: thread owns 2 contiguous features (half2), MLP=4
    const size_t brow = (size_t)b * NND;
    const unsigned int* __restrict__ ph =
        reinterpret_cast<const unsigned int*>(g_proj2h);
    float2 A0 = make_float2(0,0), A1 = make_float2(0,0);
    float2 A2 = make_float2(0,0), A3 = make_float2(0,0);
    int n = 0;
    for (; n + 3 < cnt; n += 4) {
        unsigned int r0 = ph[(brow + nbrs[wid][n    ]) * 32 + lane];
        unsigned int r1 = ph[(brow + nbrs[wid][n + 1]) * 32 + lane];
        unsigned int r2 = ph[(brow + nbrs[wid][n + 2]) * 32 + lane];
        unsigned int r3 = ph[(brow + nbrs[wid][n + 3]) * 32 + lane];
        float w0 = wts[wid][n],   w1 = wts[wid][n+1];
        float w2 = wts[wid][n+2], w3 = wts[wid][n+3];
        float2 v0 = __half22float2(*reinterpret_cast<__half2*>(&r0));
        float2 v1 = __half22float2(*reinterpret_cast<__half2*>(&r1));
        float2 v2 = __half22float2(*reinterpret_cast<__half2*>(&r2));
        float2 v3 = __half22float2(*reinterpret_cast<__half2*>(&r3));
        A0.x += w0*v0.x; A0.y += w0*v0.y;
        A1.x += w1*v1.x; A1.y += w1*v1.y;
        A2.x += w2*v2.x; A2.y += w2*v2.y;
        A3.x += w3*v3.x; A3.y += w3*v3.y;
    }
    for (; n < cnt; ++n) {
        unsigned int r0 = ph[(brow + nbrs[wid][n]) * 32 + lane];
        float w0 = wts[wid][n];
        float2 v0 = __half22float2(*reinterpret_cast<__half2*>(&r0));
        A0.x += w0*v0.x; A0.y += w0*v0.y;
    }
    const int p = lane << 1;
    float2 sk = *reinterpret_cast<const float2*>(g_skip2 + (size_t)row * F2C + p);
    float2 bb = *reinterpret_cast<const float2*>(bias + p);
    float2 o = make_float2((A0.x + A1.x) + (A2.x + A3.x) + sk.x + bb.x,
                           (A0.y + A1.y) + (A2.y + A3.y) + sk.y + bb.y);
    *reinterpret_cast<float2*>(out + (size_t)row * F2C + p) = o;
}

// ---------------------------------------------------------------------------
extern "C" void kernel_launch(void* const* d_in, const int* in_sizes, int n_in,
                              void* d_out, int out_size) {
    const float* x     = (const float*)d_in[0];
    const float* adj   = (const float*)d_in[1];
    const float* W1    = (const float*)d_in[2];
    const float* asrc1 = (const float*)d_in[3];
    const float* atgt1 = (const float*)d_in[4];
    const float* Wsk1  = (const float*)d_in[5];
    const float* b1    = (const float*)d_in[6];
    const float* W2    = (const float*)d_in[7];
    const float* asrc2 = (const float*)d_in[8];
    const float* atgt2 = (const float*)d_in[9];
    const float* Wsk2  = (const float*)d_in[10];
    const float* b2    = (const float*)d_in[11];
    float* out = (float*)d_out;

    float *proj1, *skip1, *h1;
    cudaGetSymbolAddress((void**)&proj1, g_proj1);
    cudaGetSymbolAddress((void**)&skip1, g_skip1);
    cudaGetSymbolAddress((void**)&h1,    g_h1);

    // Neighbor lists (shared by both layers)
    build_nbrs<<<dim3(NND, BSZ), 256>>>(adj);
    // Layer 1: proj+skip GEMM (4096 x 1024 x 128) + fp16 proj copy
    gemm128<FIN, FIN, HF1, false, true><<<dim3(8, 32, 1), 256>>>(
        x, W1, Wsk1, proj1, skip1);
    // Layer 1 scores (fp32 proj)
    scores1_kernel<<<MROW, 256>>>(asrc1, atgt1);
    // Layer 1 sparse attention + skip + bias + ELU -> g_h1
    att1_kernel<<<dim3(NND, BSZ), 128>>>(b1);
    // Layer 2: proj+skip GEMM (4096 x 128 x 512), split-K=4
    gemm128<HF1, HF1 / KSPLIT, F2C, true, false><<<dim3(1, 32, KSPLIT), 256>>>(
        h1, W2, Wsk2, nullptr, nullptr);
    // Fused split-K reduce + layer-2 scores (+fp16 proj2)
    reduce_scores2<<<MROW / 8, 256>>>(asrc2, atgt2);
    // Layer 2 sparse attention + skip + bias
    att2_kernel<<<dim3(NND / 4, BSZ), 128>>>(b2, out);
}

// round 7
// speedup vs baseline: 1.5003x; 1.0931x over previous
#include <cuda_runtime.h>
#include <cuda_fp16.h>
#include <math.h>

// Problem constants
#define BSZ  2
#define NND  2048
#define FIN  128
#define H1C  8
#define HF1  512      // H1*F1
#define F2C  64
#define MROW 4096     // BSZ*NND
#define MAXN 128      // neighbor cap (binomial mean ~41, sd ~6.3)
#define KSPLIT 4      // split-K factor for layer-2 GEMM

// ---------------- scratch (static device memory; no allocs) ----------------
__device__ __half g_proj1h[BSZ*NND*HF1];    // fp16 proj1 (gather operand)
__device__ float  g_skip1 [BSZ*NND*HF1];
__device__ float  g_h1    [BSZ*NND*HF1];
__device__ __half g_proj2h[BSZ*NND*F2C];
__device__ float  g_skip2 [BSZ*NND*F2C];
__device__ float  g_ssrc1 [MROW*H1C];       // [m][h]
__device__ float  g_stgt1t[H1C*MROW];       // [h][m]  (transposed: 8KB L1 window per (h,b))
__device__ float  g_ssrc2 [MROW];
__device__ float  g_stgt2 [MROW];
__device__ int    g_nbrs[MROW*MAXN];
__device__ int    g_cnt [MROW];
__device__ float  g_part[KSPLIT*(size_t)MROW*128];  // split-K partials

// ============ fused: layer-1 GEMM (+fp16 proj, +scores) ∥ nbr build ========
// Blocks [0,256): 128x128 GEMM tiles of  [x @ [W1;Wsk1]^T].
//   bx<4 -> proj columns: store fp16 + compute s_src/s_tgt from fp32 acc.
//   bx>=4 -> skip columns: store fp32.
// Blocks [256, 256+4096): adjacency-row -> neighbor list (ballot + scan).
__global__ void __launch_bounds__(256) fused1(
    const float* __restrict__ x,     const float* __restrict__ W1,
    const float* __restrict__ Wsk1,  const float* __restrict__ asrc,
    const float* __restrict__ atgt,  const float* __restrict__ adj) {
    __shared__ __align__(16) float As[16][132];   // [k][m]
    __shared__ __align__(16) float Bs[16][132];   // [k][n]
    __shared__ unsigned int words[64];

    const int tid = threadIdx.x;

    if (blockIdx.x >= 256) {
        // ---------------- neighbor build ----------------
        const int bid  = (int)blockIdx.x - 256;
        const int i    = bid & (NND - 1);
        const int b    = bid >> 11;
        const int lane = tid & 31;
        const int wid  = tid >> 5;
        const int row  = b * NND + i;
        const size_t arow = (size_t)row * NND;
        #pragma unroll
        for (int it = 0; it < 8; ++it) {
            int j = (((wid << 3) + it) << 5) + lane;
            unsigned m = __ballot_sync(0xffffffffu, adj[arow + j] != 0.0f);
            if (lane == 0) words[(wid << 3) + it] = m;
        }
        __syncthreads();
        if (wid == 0) {
            int base = 0;
            #pragma unroll
            for (int r = 0; r < 2; ++r) {
                unsigned w = words[(r << 5) + lane];
                int c = __popc(w);
                int inc = c;
                #pragma unroll
                for (int d = 1; d < 32; d <<= 1) {
                    int v = __shfl_up_sync(0xffffffffu, inc, d);
                    if (lane >= d) inc += v;
                }
                int start = base + inc - c;
                int jb = ((r << 5) + lane) << 5;
                while (w) {
                    int bit = __ffs(w) - 1;
                    w &= w - 1;
                    if (start < MAXN) g_nbrs[(size_t)row * MAXN + start] = jb + bit;
                    ++start;
                }
                base += __shfl_sync(0xffffffffu, inc, 31);
            }
            if (lane == 0) g_cnt[row] = (base < MAXN) ? base : MAXN;
        }
        return;
    }

    // ---------------- GEMM tile ----------------
    const int bx = blockIdx.x & 7;
    const int by = blockIdx.x >> 3;
    const int tx = tid & 15;
    const int ty = tid >> 4;
    const int m0 = by << 7;
    const int n0 = bx << 7;

    float acc[8][8];
    #pragma unroll
    for (int r = 0; r < 8; ++r)
        #pragma unroll
        for (int c = 0; c < 8; ++c) acc[r][c] = 0.f;

    for (int kt = 0; kt < FIN; kt += 16) {
        #pragma unroll
        for (int l = 0; l < 2; ++l) {
            int idx = tid + (l << 8);             // 0..511
            int r   = idx >> 2;                   // 0..127
            int kq  = (idx & 3) << 2;             // 0,4,8,12
            float4 av = *reinterpret_cast<const float4*>(
                x + (size_t)(m0 + r) * FIN + kt + kq);
            As[kq+0][r] = av.x; As[kq+1][r] = av.y;
            As[kq+2][r] = av.z; As[kq+3][r] = av.w;
            int og = n0 + r;
            const float* Bp = (og < HF1) ? (W1 + (size_t)og * FIN)
                                         : (Wsk1 + (size_t)(og - HF1) * FIN);
            float4 bv = *reinterpret_cast<const float4*>(Bp + kt + kq);
            Bs[kq+0][r] = bv.x; Bs[kq+1][r] = bv.y;
            Bs[kq+2][r] = bv.z; Bs[kq+3][r] = bv.w;
        }
        __syncthreads();

        #pragma unroll
        for (int k = 0; k < 16; ++k) {
            float4 a0 = *reinterpret_cast<const float4*>(&As[k][ty << 2]);
            float4 a1 = *reinterpret_cast<const float4*>(&As[k][64 + (ty << 2)]);
            float4 b0 = *reinterpret_cast<const float4*>(&Bs[k][tx << 2]);
            float4 b1 = *reinterpret_cast<const float4*>(&Bs[k][64 + (tx << 2)]);
            float a[8] = { a0.x, a0.y, a0.z, a0.w, a1.x, a1.y, a1.z, a1.w };
            float bb[8] = { b0.x, b0.y, b0.z, b0.w, b1.x, b1.y, b1.z, b1.w };
            #pragma unroll
            for (int r = 0; r < 8; ++r)
                #pragma unroll
                for (int c = 0; c < 8; ++c)
                    acc[r][c] += a[r] * bb[c];
        }
        __syncthreads();
    }

    if (bx < 4) {
        // proj columns: fp16 stores + fused attention scores
        const int hA = bx << 1, hB = hA + 1;
        float4 asA = *reinterpret_cast<const float4*>(asrc + hA * 64 + (tx << 2));
        float4 atA = *reinterpret_cast<const float4*>(atgt + hA * 64 + (tx << 2));
        float4 asB = *reinterpret_cast<const float4*>(asrc + hB * 64 + (tx << 2));
        float4 atB = *reinterpret_cast<const float4*>(atgt + hB * 64 + (tx << 2));

        #pragma unroll
        for (int r = 0; r < 8; ++r) {
            int m = m0 + ((r & 4) << 4) + (ty << 2) + (r & 3);
            #pragma unroll
            for (int ch = 0; ch < 2; ++ch) {
                int colloc = (ch << 6) + (tx << 2);
                float4 v = make_float4(acc[r][(ch<<2)+0], acc[r][(ch<<2)+1],
                                       acc[r][(ch<<2)+2], acc[r][(ch<<2)+3]);
                __half2 h01 = __floats2half2_rn(v.x, v.y);
                __half2 h23 = __floats2half2_rn(v.z, v.w);
                uint2 pk;
                pk.x = *reinterpret_cast<unsigned int*>(&h01);
                pk.y = *reinterpret_cast<unsigned int*>(&h23);
                *reinterpret_cast<uint2*>(
                    g_proj1h + (size_t)m * HF1 + n0 + colloc) = pk;
            }
            float ssA = acc[r][0]*asA.x + acc[r][1]*asA.y
                      + acc[r][2]*asA.z + acc[r][3]*asA.w;
            float stA = acc[r][0]*atA.x + acc[r][1]*atA.y
                      + acc[r][2]*atA.z + acc[r][3]*atA.w;
            float ssB = acc[r][4]*asB.x + acc[r][5]*asB.y
                      + acc[r][6]*asB.z + acc[r][7]*asB.w;
            float stB = acc[r][4]*atB.x + acc[r][5]*atB.y
                      + acc[r][6]*atB.z + acc[r][7]*atB.w;
            #pragma unroll
            for (int d = 1; d < 16; d <<= 1) {
                ssA += __shfl_xor_sync(0xffffffffu, ssA, d);
                stA += __shfl_xor_sync(0xffffffffu, stA, d);
                ssB += __shfl_xor_sync(0xffffffffu, ssB, d);
                stB += __shfl_xor_sync(0xffffffffu, stB, d);
            }
            if (tx == 0) {
                g_ssrc1[m * H1C + hA] = ssA;
                g_ssrc1[m * H1C + hB] = ssB;
                g_stgt1t[hA * MROW + m] = stA;
                g_stgt1t[hB * MROW + m] = stB;
            }
        }
    } else {
        // skip columns: fp32 stores
        #pragma unroll
        for (int r = 0; r < 8; ++r) {
            int m = m0 + ((r & 4) << 4) + (ty << 2) + (r & 3);
            #pragma unroll
            for (int ch = 0; ch < 2; ++ch) {
                int colloc = (ch << 6) + (tx << 2);
                float4 v = make_float4(acc[r][(ch<<2)+0], acc[r][(ch<<2)+1],
                                       acc[r][(ch<<2)+2], acc[r][(ch<<2)+3]);
                int og = n0 + colloc - HF1;
                *reinterpret_cast<float4*>(
                    g_skip1 + (size_t)m * HF1 + og) = v;
            }
        }
    }
}

// ========== layer-1 attention: reg-resident softmax + HFMA2 gather =========
__global__ void __launch_bounds__(128) att1_kernel(const float* __restrict__ bias) {
    __shared__ int     noff[MAXN];          // (brow+j)*128  (uint2 row base)
    __shared__ __half2 wts2[H1C][MAXN];     // normalized weights, duplicated

    const int i    = blockIdx.x;
    const int b    = blockIdx.y;
    const int tid  = threadIdx.x;
    const int lane = tid & 31;
    const int wid  = tid >> 5;              // 0..3
    const int row  = b * NND + i;
    const int brow = b * NND;

    const int cnt = g_cnt[row];
    for (int n = tid; n < cnt; n += 128)
        noff[n] = (brow + g_nbrs[(size_t)row * MAXN + n]) << 7;
    __syncthreads();

    // softmax: warp w handles heads 2w, 2w+1; values live in registers
    #pragma unroll
    for (int hh = 0; hh < 2; ++hh) {
        const int h = (wid << 1) + hh;
        const float si = g_ssrc1[row * H1C + h];
        const float* __restrict__ st = g_stgt1t + h * MROW;
        float e[4];
        float mx = -3.0e38f;
        #pragma unroll
        for (int s = 0; s < 4; ++s) {
            int n = lane + (s << 5);
            float v = -3.0e38f;
            if (n < cnt) {
                float t = si + st[noff[n] >> 7];
                v = (t > 0.f) ? t : 0.2f * t;     // leaky_relu(0.2)
            }
            e[s] = v;
            mx = fmaxf(mx, v);
        }
        #pragma unroll
        for (int d = 16; d; d >>= 1)
            mx = fmaxf(mx, __shfl_xor_sync(0xffffffffu, mx, d));
        float sum = 0.f;
        #pragma unroll
        for (int s = 0; s < 4; ++s) {
            float ex = expf(e[s] - mx);           // inactive: exp(-3e38)=0
            e[s] = ex;
            sum += ex;
        }
        #pragma unroll
        for (int d = 16; d; d >>= 1)
            sum += __shfl_xor_sync(0xffffffffu, sum, d);
        float inv = 1.0f / sum;
        #pragma unroll
        for (int s = 0; s < 4; ++s) {
            int n = lane + (s << 5);
            if (n < cnt) wts2[h][n] = __float2half2_rn(e[s] * inv);
        }
    }
    __syncthreads();

    // gather: thread owns 4 features; uint2 index within row == tid
    const int h = tid >> 4;
    const uint2* __restrict__ ph = reinterpret_cast<const uint2*>(g_proj1h);
    const __half2 z = __float2half2_rn(0.f);
    __half2 a0=z, b0=z, a1=z, b1=z, a2=z, b2=z, a3=z, b3=z;
    int n = 0;
    for (; n + 3 < cnt; n += 4) {
        int o0 = noff[n], o1 = noff[n+1], o2 = noff[n+2], o3 = noff[n+3];
        __half2 w0 = wts2[h][n],   w1 = wts2[h][n+1];
        __half2 w2 = wts2[h][n+2], w3 = wts2[h][n+3];
        uint2 r0 = ph[o0 + tid];
        uint2 r1 = ph[o1 + tid];
        uint2 r2 = ph[o2 + tid];
        uint2 r3 = ph[o3 + tid];
        a0 = __hfma2(w0, *reinterpret_cast<__half2*>(&r0.x), a0);
        b0 = __hfma2(w0, *reinterpret_cast<__half2*>(&r0.y), b0);
        a1 = __hfma2(w1, *reinterpret_cast<__half2*>(&r1.x), a1);
        b1 = __hfma2(w1, *reinterpret_cast<__half2*>(&r1.y), b1);
        a2 = __hfma2(w2, *reinterpret_cast<__half2*>(&r2.x), a2);
        b2 = __hfma2(w2, *reinterpret_cast<__half2*>(&r2.y), b2);
        a3 = __hfma2(w3, *reinterpret_cast<__half2*>(&r3.x), a3);
        b3 = __hfma2(w3, *reinterpret_cast<__half2*>(&r3.y), b3);
    }
    for (; n < cnt; ++n) {
        int o = noff[n];
        __half2 w = wts2[h][n];
        uint2 r = ph[o + tid];
        a0 = __hfma2(w, *reinterpret_cast<__half2*>(&r.x), a0);
        b0 = __hfma2(w, *reinterpret_cast<__half2*>(&r.y), b0);
    }
    float2 fa0 = __half22float2(a0), fa1 = __half22float2(a1);
    float2 fa2 = __half22float2(a2), fa3 = __half22float2(a3);
    float2 fb0 = __half22float2(b0), fb1 = __half22float2(b1);
    float2 fb2 = __half22float2(b2), fb3 = __half22float2(b3);
    float sx = (fa0.x + fa1.x) + (fa2.x + fa3.x);
    float sy = (fa0.y + fa1.y) + (fa2.y + fa3.y);
    float sz = (fb0.x + fb1.x) + (fb2.x + fb3.x);
    float sw = (fb0.y + fb1.y) + (fb2.y + fb3.y);

    const int p = tid << 2;
    float4 sk = *reinterpret_cast<const float4*>(g_skip1 + (size_t)row * HF1 + p);
    float4 bb = *reinterpret_cast<const float4*>(bias + p);
    float4 o;
    o.x = sx + sk.x + bb.x;
    o.y = sy + sk.y + bb.y;
    o.z = sz + sk.z + bb.z;
    o.w = sw + sk.w + bb.w;
    o.x = (o.x > 0.f) ? o.x : expm1f(o.x);
    o.y = (o.y > 0.f) ? o.y : expm1f(o.y);
    o.z = (o.z > 0.f) ? o.z : expm1f(o.z);
    o.w = (o.w > 0.f) ? o.w : expm1f(o.w);
    *reinterpret_cast<float4*>(g_h1 + (size_t)row * HF1 + p) = o;
}

// ================== layer-2 GEMM: g_h1 @ [W2;Wsk2]^T, split-K ==============
__global__ void __launch_bounds__(256) gemm2_kernel(
    const float* __restrict__ W2, const float* __restrict__ Wsk2) {
    __shared__ __align__(16) float As[16][132];
    __shared__ __align__(16) float Bs[16][132];

    const int tid = threadIdx.x;
    const int tx  = tid & 15;
    const int ty  = tid >> 4;
    const int m0  = blockIdx.y << 7;
    const int kz  = blockIdx.z * (HF1 / KSPLIT);

    float acc[8][8];
    #pragma unroll
    for (int r = 0; r < 8; ++r)
        #pragma unroll
        for (int c = 0; c < 8; ++c) acc[r][c] = 0.f;

    for (int kt = kz; kt < kz + HF1 / KSPLIT; kt += 16) {
        #pragma unroll
        for (int l = 0; l < 2; ++l) {
            int idx = tid + (l << 8);
            int r   = idx >> 2;
            int kq  = (idx & 3) << 2;
            float4 av = *reinterpret_cast<const float4*>(
                g_h1 + (size_t)(m0 + r) * HF1 + kt + kq);
            As[kq+0][r] = av.x; As[kq+1][r] = av.y;
            As[kq+2][r] = av.z; As[kq+3][r] = av.w;
            const float* Bp = (r < F2C) ? (W2 + (size_t)r * HF1)
                                        : (Wsk2 + (size_t)(r - F2C) * HF1);
            float4 bv = *reinterpret_cast<const float4*>(Bp + kt + kq);
            Bs[kq+0][r] = bv.x; Bs[kq+1][r] = bv.y;
            Bs[kq+2][r] = bv.z; Bs[kq+3][r] = bv.w;
        }
        __syncthreads();

        #pragma unroll
        for (int k = 0; k < 16; ++k) {
            float4 a0 = *reinterpret_cast<const float4*>(&As[k][ty << 2]);
            float4 a1 = *reinterpret_cast<const float4*>(&As[k][64 + (ty << 2)]);
            float4 b0 = *reinterpret_cast<const float4*>(&Bs[k][tx << 2]);
            float4 b1 = *reinterpret_cast<const float4*>(&Bs[k][64 + (tx << 2)]);
            float a[8] = { a0.x, a0.y, a0.z, a0.w, a1.x, a1.y, a1.z, a1.w };
            float bb[8] = { b0.x, b0.y, b0.z, b0.w, b1.x, b1.y, b1.z, b1.w };
            #pragma unroll
            for (int r = 0; r < 8; ++r)
                #pragma unroll
                for (int c = 0; c < 8; ++c)
                    acc[r][c] += a[r] * bb[c];
        }
        __syncthreads();
    }

    #pragma unroll
    for (int r = 0; r < 8; ++r) {
        int m = m0 + ((r & 4) << 4) + (ty << 2) + (r & 3);
        #pragma unroll
        for (int ch = 0; ch < 2; ++ch) {
            int colloc = (ch << 6) + (tx << 2);
            float4 v = make_float4(acc[r][(ch<<2)+0], acc[r][(ch<<2)+1],
                                   acc[r][(ch<<2)+2], acc[r][(ch<<2)+3]);
            *reinterpret_cast<float4*>(
                g_part + ((size_t)blockIdx.z * MROW + m) * 128 + colloc) = v;
        }
    }
}

// ------- fused split-K reduce + layer-2 scores (warp per row) --------------
__global__ void reduce_scores2(const float* __restrict__ a_src,
                               const float* __restrict__ a_tgt) {
    const int lane = threadIdx.x & 31;
    const int wid  = threadIdx.x >> 5;           // 0..7
    const int m    = (blockIdx.x << 3) + wid;

    float4 s = make_float4(0,0,0,0);
    #pragma unroll
    for (int z = 0; z < KSPLIT; ++z) {
        float4 v = *reinterpret_cast<const float4*>(
            g_part + ((size_t)z * MROW + m) * 128 + (lane << 2));
        s.x += v.x; s.y += v.y; s.z += v.z; s.w += v.w;
    }

    float ss = 0.f, st = 0.f;
    if (lane < 16) {
        __half2 h01 = __floats2half2_rn(s.x, s.y);
        __half2 h23 = __floats2half2_rn(s.z, s.w);
        uint2 pk;
        pk.x = *reinterpret_cast<unsigned int*>(&h01);
        pk.y = *reinterpret_cast<unsigned int*>(&h23);
        *reinterpret_cast<uint2*>(g_proj2h + (size_t)m * F2C + (lane << 2)) = pk;
        float4 as = *reinterpret_cast<const float4*>(a_src + (lane << 2));
        float4 at = *reinterpret_cast<const float4*>(a_tgt + (lane << 2));
        ss = s.x*as.x + s.y*as.y + s.z*as.z + s.w*as.w;
        st = s.x*at.x + s.y*at.y + s.z*at.z + s.w*at.w;
    } else {
        *reinterpret_cast<float4*>(
            g_skip2 + (size_t)m * F2C + ((lane - 16) << 2)) = s;
    }
    #pragma unroll
    for (int d = 16; d; d >>= 1) {
        ss += __shfl_xor_sync(0xffffffffu, ss, d);
        st += __shfl_xor_sync(0xffffffffu, st, d);
    }
    if (lane == 0) {
        g_ssrc2[m] = ss;
        g_stgt2[m] = st;
    }
}

// ========== layer-2 attention: warp/row, reg softmax + HFMA2 gather ========
__global__ void __launch_bounds__(128) att2_kernel(
    const float* __restrict__ bias, float* __restrict__ out) {
    __shared__ int     noff[4][MAXN];       // (brow+j)*32  (half2 row base)
    __shared__ __half2 wts2[4][MAXN];

    const int b    = blockIdx.y;
    const int tid  = threadIdx.x;
    const int lane = tid & 31;
    const int wid  = tid >> 5;              // 0..3
    const int i    = (blockIdx.x << 2) + wid;
    const int row  = b * NND + i;
    const int brow = b * NND;

    const int cnt = g_cnt[row];
    for (int n = lane; n < cnt; n += 32)
        noff[wid][n] = (brow + g_nbrs[(size_t)row * MAXN + n]) << 5;
    __syncwarp();

    {
        const float si = g_ssrc2[row];
        float e[4];
        float mx = -3.0e38f;
        #pragma unroll
        for (int s = 0; s < 4; ++s) {
            int n = lane + (s << 5);
            float v = -3.0e38f;
            if (n < cnt) {
                float t = si + g_stgt2[noff[wid][n] >> 5];
                v = (t > 0.f) ? t : 0.2f * t;
            }
            e[s] = v;
            mx = fmaxf(mx, v);
        }
        #pragma unroll
        for (int d = 16; d; d >>= 1)
            mx = fmaxf(mx, __shfl_xor_sync(0xffffffffu, mx, d));
        float sum = 0.f;
        #pragma unroll
        for (int s = 0; s < 4; ++s) {
            float ex = expf(e[s] - mx);
            e[s] = ex;
            sum += ex;
        }
        #pragma unroll
        for (int d = 16; d; d >>= 1)
            sum += __shfl_xor_sync(0xffffffffu, sum, d);
        float inv = 1.0f / sum;
        #pragma unroll
        for (int s = 0; s < 4; ++s) {
            int n = lane + (s << 5);
            if (n < cnt) wts2[wid][n] = __float2half2_rn(e[s] * inv);
        }
    }
    __syncwarp();

    // gather: thread owns 2 features; half2 index within row == lane
    const unsigned int* __restrict__ ph =
        reinterpret_cast<const unsigned int*>(g_proj2h);
    const __half2 z = __float2half2_rn(0.f);
    __half2 A0=z, A1=z, A2=z, A3=z;
    int n = 0;
    for (; n + 3 < cnt; n += 4) {
        int o0 = noff[wid][n],   o1 = noff[wid][n+1];
        int o2 = noff[wid][n+2], o3 = noff[wid][n+3];
        __half2 w0 = wts2[wid][n],   w1 = wts2[wid][n+1];
        __half2 w2 = wts2[wid][n+2], w3 = wts2[wid][n+3];
        unsigned int r0 = ph[o0 + lane];
        unsigned int r1 = ph[o1 + lane];
        unsigned int r2 = ph[o2 + lane];
        unsigned int r3 = ph[o3 + lane];
        A0 = __hfma2(w0, *reinterpret_cast<__half2*>(&r0), A0);
        A1 = __hfma2(w1, *reinterpret_cast<__half2*>(&r1), A1);
        A2 = __hfma2(w2, *reinterpret_cast<__half2*>(&r2), A2);
        A3 = __hfma2(w3, *reinterpret_cast<__half2*>(&r3), A3);
    }
    for (; n < cnt; ++n) {
        int o = noff[wid][n];
        __half2 w = wts2[wid][n];
        unsigned int r = ph[o + lane];
        A0 = __hfma2(w, *reinterpret_cast<__half2*>(&r), A0);
    }
    float2 f0 = __half22float2(A0), f1 = __half22float2(A1);
    float2 f2 = __half22float2(A2), f3 = __half22float2(A3);
    const int p = lane << 1;
    float2 sk = *reinterpret_cast<const float2*>(g_skip2 + (size_t)row * F2C + p);
    float2 bb = *reinterpret_cast<const float2*>(bias + p);
    float2 o = make_float2((f0.x + f1.x) + (f2.x + f3.x) + sk.x + bb.x,
                           (f0.y + f1.y) + (f2.y + f3.y) + sk.y + bb.y);
    *reinterpret_cast<float2*>(out + (size_t)row * F2C + p) = o;
}

// ---------------------------------------------------------------------------
extern "C" void kernel_launch(void* const* d_in, const int* in_sizes, int n_in,
                              void* d_out, int out_size) {
    const float* x     = (const float*)d_in[0];
    const float* adj   = (const float*)d_in[1];
    const float* W1    = (const float*)d_in[2];
    const float* asrc1 = (const float*)d_in[3];
    const float* atgt1 = (const float*)d_in[4];
    const float* Wsk1  = (const float*)d_in[5];
    const float* b1    = (const float*)d_in[6];
    const float* W2    = (const float*)d_in[7];
    const float* asrc2 = (const float*)d_in[8];
    const float* atgt2 = (const float*)d_in[9];
    const float* Wsk2  = (const float*)d_in[10];
    const float* b2    = (const float*)d_in[11];
    float* out = (float*)d_out;

    // 1. fused: layer-1 GEMM(+fp16 proj, +scores)  ∥  neighbor build
    fused1<<<256 + MROW, 256>>>(x, W1, Wsk1, asrc1, atgt1, adj);
    // 2. layer-1 sparse attention + skip + bias + ELU -> g_h1
    att1_kernel<<<dim3(NND, BSZ), 128>>>(b1);
    // 3. layer-2 GEMM (4096 x 128 x 512), split-K
    gemm2_kernel<<<dim3(1, 32, KSPLIT), 256>>>(W2, Wsk2);
    // 4. fused split-K reduce + layer-2 scores (+fp16 proj2)
    reduce_scores2<<<MROW / 8, 256>>>(asrc2, atgt2);
    // 5. layer-2 sparse attention + skip + bias
    att2_kernel<<<dim3(NND / 4, BSZ), 128>>>(b2, out);
}